// round 9
// baseline (speedup 1.0000x reference)
#include <cuda_runtime.h>
#include <cuda_bf16.h>
#include <math.h>

// Problem constants (fixed by reference setup_inputs)
#define BB 8
#define TT 16
#define CC 64
#define NN 4096          // H*W
#define KSEL 2048        // keep_k = N*(1-0.5)

#define CHUNKB 2                          // batches per chunk
#define CGROUPS 4                         // c-split for full-thread-count K1
#define CPER 16                           // channels per group
#define BLKS_PER_BATCH 256                // K1 blocks per batch (524288/2/1024)

// Scratch (device globals — no allocation allowed)
__device__ float g_partial4[BB * TT * CGROUPS * NN];  // sum(x^2) per (b,t,cg,n), 8 MB
__device__ unsigned g_maskbits[BB * (NN / 32)];       // 1 bit per (b,n)
__device__ int g_cnt[BB];                             // per-batch counters (self-resetting)

__device__ __forceinline__ unsigned long long warp_sum_u64(unsigned long long v) {
#pragma unroll
    for (int d = 16; d; d >>= 1) v += __shfl_xor_sync(0xffffffffu, v, d);
    return v;
}

// ---------------------------------------------------------------------------
// Select body (verified radix structure; scores now combine 4 group sums
// before the sqrt). 1024 threads of one block; exact top-K -> mask bits.
// ---------------------------------------------------------------------------
__device__ void select_body(int b) {
    __shared__ unsigned long long s_red64[2][32];
    __shared__ unsigned s_u32[66];
    __shared__ unsigned s_mask[NN / 32];
    __shared__ int s_scan[32];
    __shared__ int s_int[1];

    const int j    = threadIdx.x;              // 0..1023
    const int lane = j & 31;
    const int wid  = j >> 5;

    // --- scores: 4 n per thread; per t: sum 4 group partials, sqrt, accum ---
    const float4* part = (const float4*)g_partial4;
    float s0 = 0.f, s1 = 0.f, s2 = 0.f, s3 = 0.f;
#pragma unroll
    for (int t = 0; t < TT; ++t) {
        size_t base = (size_t)(b * TT + t) * CGROUPS * (NN / 4);
        float4 p0 = part[base + 0 * (NN / 4) + j];
        float4 p1 = part[base + 1 * (NN / 4) + j];
        float4 p2 = part[base + 2 * (NN / 4) + j];
        float4 p3 = part[base + 3 * (NN / 4) + j];
        s0 += sqrtf(p0.x + p1.x + p2.x + p3.x);
        s1 += sqrtf(p0.y + p1.y + p2.y + p3.y);
        s2 += sqrtf(p0.z + p1.z + p2.z + p3.z);
        s3 += sqrtf(p0.w + p1.w + p2.w + p3.w);
    }
    const float inv = 1.0f / (float)TT;
    unsigned u0 = __float_as_uint(s0 * inv);
    unsigned u1 = __float_as_uint(s1 * inv);
    unsigned u2 = __float_as_uint(s2 * inv);
    unsigned u3 = __float_as_uint(s3 * inv);

    if (j < NN / 32) s_mask[j] = 0u;

    // --- block OR / AND of all score bits ---
    unsigned ov = u0 | u1 | u2 | u3;
    unsigned av = u0 & u1 & u2 & u3;
#pragma unroll
    for (int d = 16; d; d >>= 1) {
        ov |= __shfl_xor_sync(0xffffffffu, ov, d);
        av &= __shfl_xor_sync(0xffffffffu, av, d);
    }
    if (lane == 0) { s_u32[wid] = ov; s_u32[32 + wid] = av; }
    __syncthreads();
    {
        unsigned o2 = s_u32[lane], a2 = s_u32[32 + lane];
#pragma unroll
        for (int d = 16; d; d >>= 1) {
            o2 |= __shfl_xor_sync(0xffffffffu, o2, d);
            a2 &= __shfl_xor_sync(0xffffffffu, a2, d);
        }
        if (j == 0) { s_u32[64] = o2; s_u32[65] = a2; }
    }
    __syncthreads();
    const unsigned orv  = s_u32[64];
    const unsigned andv = s_u32[65];
    const unsigned diff = orv ^ andv;

    // --- 2-bit radix select: largest thr with count(u >= thr) >= KSEL ---
    unsigned thr = 0u;
    int par = 0;
#pragma unroll
    for (int p = 15; p >= 0; --p) {
        unsigned m2 = 3u << (2 * p);
        if ((diff & m2) == 0u) {               // both bits uniform across block
            thr |= (andv & m2);
            continue;
        }
        unsigned c1 = thr | (1u << (2 * p));
        unsigned c2 = thr | (2u << (2 * p));
        unsigned c3 = thr | (3u << (2 * p));
        int n1 = (u0 >= c1) + (u1 >= c1) + (u2 >= c1) + (u3 >= c1);
        int n2 = (u0 >= c2) + (u1 >= c2) + (u2 >= c2) + (u3 >= c2);
        int n3 = (u0 >= c3) + (u1 >= c3) + (u2 >= c3) + (u3 >= c3);
        unsigned long long pk = (unsigned long long)n1
                              | ((unsigned long long)n2 << 20)
                              | ((unsigned long long)n3 << 40);
        pk = warp_sum_u64(pk);
        if (lane == 0) s_red64[par][wid] = pk;
        __syncthreads();
        unsigned long long tot = warp_sum_u64(s_red64[par][lane]);
        int N1 = (int)(tot & 0xFFFFFull);
        int N2 = (int)((tot >> 20) & 0xFFFFFull);
        int N3 = (int)((tot >> 40) & 0xFFFFFull);
        if      (N3 >= KSEL) thr = c3;
        else if (N2 >= KSEL) thr = c2;
        else if (N1 >= KSEL) thr = c1;
        par ^= 1;
    }
    __syncthreads();   // protect s_red64 before reuse below

    // --- strictly-greater count (ties admitted by lowest index) ---
    {
        unsigned long long pk =
            (unsigned long long)((u0 > thr) + (u1 > thr) + (u2 > thr) + (u3 > thr));
        pk = warp_sum_u64(pk);
        if (lane == 0) s_red64[0][wid] = pk;
        __syncthreads();
        unsigned long long tot = warp_sum_u64(s_red64[0][lane]);
        if (j == 0) s_int[0] = (int)tot;
        __syncthreads();
    }
    int need = KSEL - s_int[0];

    // --- exclusive scan over threads of per-thread equal-count ---
    int e = (u0 == thr) + (u1 == thr) + (u2 == thr) + (u3 == thr);
    int v = e;
#pragma unroll
    for (int d = 1; d < 32; d <<= 1) {
        int t = __shfl_up_sync(0xffffffffu, v, d);
        if (lane >= d) v += t;
    }
    if (lane == 31) s_scan[wid] = v;
    __syncthreads();
    if (wid == 0) {
        int w = s_scan[lane];
#pragma unroll
        for (int d = 1; d < 32; d <<= 1) {
            int t = __shfl_up_sync(0xffffffffu, w, d);
            if (lane >= d) w += t;
        }
        s_scan[lane] = w;
    }
    __syncthreads();
    int excl = v - e + (wid ? s_scan[wid - 1] : 0);

    // --- mask nibble for n = 4j..4j+3 ---
    unsigned nib = 0;
    int r = excl;
    unsigned uu[4] = {u0, u1, u2, u3};
#pragma unroll
    for (int i = 0; i < 4; ++i) {
        if (uu[i] > thr) {
            nib |= 1u << i;
        } else if (uu[i] == thr) {
            if (r < need) nib |= 1u << i;
            ++r;
        }
    }
    atomicOr(&s_mask[j >> 3], nib << ((j & 7) * 4));
    __syncthreads();
    if (j < NN / 32) g_maskbits[b * (NN / 32) + j] = s_mask[j];
}

// ---------------------------------------------------------------------------
// K1: per-chunk scoring with FULL thread count (524288 threads/chunk): the
// c-reduction is split into 4 groups of 16, so every thread does 16 strided
// loads and aggregate MLP matches the 5.7 TB/s monolithic k_partial.
// Last block per batch (threadfence+counter) runs select in-kernel.
// ---------------------------------------------------------------------------
__global__ void __launch_bounds__(1024) k1_score_select(const float* __restrict__ x,
                                                        int chunk) {
    const int idx = blockIdx.x * 1024 + threadIdx.x;   // [0, 524288)
    const int n   = idx & (NN - 1);
    const int cg  = (idx >> 12) & (CGROUPS - 1);
    const int btl = idx >> 14;                         // 0..31
    const int b   = chunk * CHUNKB + (btl >> 4);
    const int bt  = chunk * (CHUNKB * TT) + btl;       // global b*TT + t

    const float* p = x + (size_t)bt * CC * NN + (size_t)(cg * CPER) * NN + n;
    float acc = 0.0f;
#pragma unroll
    for (int c = 0; c < CPER; ++c) {
        float v = p[(size_t)c * NN];
        acc += v * v;
    }
    g_partial4[((size_t)bt * CGROUPS + cg) * NN + n] = acc;

    // --- last-block-per-batch detection ---
    __shared__ int s_last;
    __syncthreads();
    if (threadIdx.x == 0) {
        __threadfence();
        int vv = atomicAdd(&g_cnt[b], 1);
        s_last = (vv == BLKS_PER_BATCH - 1);
        if (s_last) g_cnt[b] = 0;          // self-reset for graph replay
    }
    __syncthreads();
    if (!s_last) return;

    __threadfence();                        // acquire: see all partial writes
    select_body(b);
}

// ---------------------------------------------------------------------------
// M: masked copy for one chunk; reads hit x[chunk]'s L2 residue from K1.
// ---------------------------------------------------------------------------
__global__ void __launch_bounds__(256) k_mask(const float4* __restrict__ x4,
                                              float4* __restrict__ o4,
                                              int chunk) {
    unsigned i = (unsigned)chunk * (CHUNKB * TT * CC * NN / 4)
               + blockIdx.x * 256 + threadIdx.x;
    int n4 = i & ((NN / 4) - 1);
    int b  = i >> 20;                        // 2^20 float4 per batch
    int n  = n4 << 2;
    unsigned mword = g_maskbits[(b << 7) + (n >> 5)];
    unsigned bits  = mword >> (n & 31);
    float4 v = __ldcs(&x4[(size_t)i]);
    v.x = (bits & 1u) ? v.x : 0.0f;
    v.y = (bits & 2u) ? v.y : 0.0f;
    v.z = (bits & 4u) ? v.z : 0.0f;
    v.w = (bits & 8u) ? v.w : 0.0f;
    __stcs(&o4[(size_t)i], v);
}

// ---------------------------------------------------------------------------
extern "C" void kernel_launch(void* const* d_in, const int* in_sizes, int n_in,
                              void* d_out, int out_size) {
    const float* x = (const float*)d_in[0];
    float* out = (float*)d_out;

    const int K1_GRID = CHUNKB * TT * CGROUPS * NN / 1024;  // 512 blocks
    const int M_GRID  = CHUNKB * TT * CC * NN / 4 / 256;    // 8192 blocks

    // Software pipeline: M(c) runs one chunk behind K1, so x[c] is still
    // L2-resident when M(c) re-reads it.
    k1_score_select<<<K1_GRID, 1024>>>(x, 0);
    k1_score_select<<<K1_GRID, 1024>>>(x, 1);
    k_mask<<<M_GRID, 256>>>((const float4*)x, (float4*)out, 0);
    k1_score_select<<<K1_GRID, 1024>>>(x, 2);
    k_mask<<<M_GRID, 256>>>((const float4*)x, (float4*)out, 1);
    k1_score_select<<<K1_GRID, 1024>>>(x, 3);
    k_mask<<<M_GRID, 256>>>((const float4*)x, (float4*)out, 2);
    k_mask<<<M_GRID, 256>>>((const float4*)x, (float4*)out, 3);
}

// round 10
// speedup vs baseline: 1.0274x; 1.0274x over previous
#include <cuda_runtime.h>
#include <cuda_bf16.h>
#include <math.h>

// Problem constants (fixed by reference setup_inputs)
#define BB 8
#define TT 16
#define CC 64
#define NN 4096          // H*W
#define KSEL 2048        // keep_k = N*(1-0.5)

#define CGROUPS 4        // c-split: 16 channels per group
#define CPER 16
#define BLKS_PER_BATCH 256   // 65536 threads per batch / 256
#define NHELP 8              // helper blocks per batch for score reduction

typedef unsigned long long ull;

// Scratch (device globals — no allocation allowed; zero-init, self-resetting)
__device__ float g_partial4[BB * TT * CGROUPS * NN];  // sum(x^2) per (b,t,cg,n), 8 MB
__device__ float g_scores[BB * NN];                   // per-(b,n) final scores
__device__ unsigned g_maskbits[BB * (NN / 32)];       // 1 bit per (b,n)
__device__ int g_cnt[BB];    // blocks-done-streaming counter
__device__ int g_cnt2[BB];   // helpers-done counter
__device__ int g_cnt3[BB];   // blocks-done-writing counter (resets everything)
__device__ int g_flag[BB];   // mask-ready flag

__device__ __forceinline__ ull warp_sum_u64(ull v) {
#pragma unroll
    for (int d = 16; d; d >>= 1) v += __shfl_xor_sync(0xffffffffu, v, d);
    return v;
}

// ---------------------------------------------------------------------------
// Radix select, 256 threads, 16 scores per thread (n = 16j..16j+15).
// Exact top-K with lowest-index tie-break; identical semantics to the
// verified R4-R9 select body.
// ---------------------------------------------------------------------------
__device__ void radix_select_256(int b) {
    __shared__ ull s64[2][8];
    __shared__ unsigned s_or[8], s_and[8];
    __shared__ int s_scan[8];
    __shared__ unsigned s_mask[NN / 32];
    __shared__ int s_need;

    const int j    = threadIdx.x;
    const int lane = j & 31;
    const int wid  = j >> 5;

    unsigned u[16];
    const float4* sc4 = (const float4*)(g_scores + b * NN);
#pragma unroll
    for (int q = 0; q < 4; ++q) {
        float4 f = sc4[j * 4 + q];
        u[q * 4 + 0] = __float_as_uint(f.x);
        u[q * 4 + 1] = __float_as_uint(f.y);
        u[q * 4 + 2] = __float_as_uint(f.z);
        u[q * 4 + 3] = __float_as_uint(f.w);
    }
    if (j < NN / 32) s_mask[j] = 0u;

    // block OR / AND of score bits
    unsigned ov = 0u, av = 0xffffffffu;
#pragma unroll
    for (int i = 0; i < 16; ++i) { ov |= u[i]; av &= u[i]; }
#pragma unroll
    for (int d = 16; d; d >>= 1) {
        ov |= __shfl_xor_sync(0xffffffffu, ov, d);
        av &= __shfl_xor_sync(0xffffffffu, av, d);
    }
    if (lane == 0) { s_or[wid] = ov; s_and[wid] = av; }
    __syncthreads();
    unsigned orv = s_or[0], andv = s_and[0];
#pragma unroll
    for (int w = 1; w < 8; ++w) { orv |= s_or[w]; andv &= s_and[w]; }
    const unsigned diff = orv ^ andv;

    // 2-bit radix: largest thr with count(u >= thr) >= KSEL
    unsigned thr = 0u;
    int par = 0;
#pragma unroll
    for (int p = 15; p >= 0; --p) {
        unsigned m2 = 3u << (2 * p);
        if ((diff & m2) == 0u) { thr |= (andv & m2); continue; }
        unsigned c1 = thr | (1u << (2 * p));
        unsigned c2 = thr | (2u << (2 * p));
        unsigned c3 = thr | (3u << (2 * p));
        int n1 = 0, n2 = 0, n3 = 0;
#pragma unroll
        for (int i = 0; i < 16; ++i) {
            n1 += (u[i] >= c1); n2 += (u[i] >= c2); n3 += (u[i] >= c3);
        }
        ull pk = (ull)n1 | ((ull)n2 << 20) | ((ull)n3 << 40);
        pk = warp_sum_u64(pk);
        if (lane == 0) s64[par][wid] = pk;
        __syncthreads();
        ull tot = 0;
#pragma unroll
        for (int w = 0; w < 8; ++w) tot += s64[par][w];
        int N1 = (int)(tot & 0xFFFFFull);
        int N2 = (int)((tot >> 20) & 0xFFFFFull);
        int N3 = (int)((tot >> 40) & 0xFFFFFull);
        if      (N3 >= KSEL) thr = c3;
        else if (N2 >= KSEL) thr = c2;
        else if (N1 >= KSEL) thr = c1;
        par ^= 1;
    }
    __syncthreads();

    // strictly-greater count
    {
        int gt = 0;
#pragma unroll
        for (int i = 0; i < 16; ++i) gt += (u[i] > thr);
        ull pk = warp_sum_u64((ull)gt);
        if (lane == 0) s64[0][wid] = pk;
        __syncthreads();
        ull tot = 0;
#pragma unroll
        for (int w = 0; w < 8; ++w) tot += s64[0][w];
        if (j == 0) s_need = KSEL - (int)tot;
    }

    // exclusive scan of equal-counts over threads (index order)
    int e = 0;
#pragma unroll
    for (int i = 0; i < 16; ++i) e += (u[i] == thr);
    int v = e;
#pragma unroll
    for (int d = 1; d < 32; d <<= 1) {
        int tv = __shfl_up_sync(0xffffffffu, v, d);
        if (lane >= d) v += tv;
    }
    if (lane == 31) s_scan[wid] = v;
    __syncthreads();
    int wpre = 0;
    for (int w = 0; w < wid; ++w) wpre += s_scan[w];
    int excl = v - e + wpre;
    int need = s_need;

    // build 16 mask bits for n = 16j..16j+15
    unsigned bits16 = 0;
    int r = excl;
#pragma unroll
    for (int i = 0; i < 16; ++i) {
        if (u[i] > thr) {
            bits16 |= 1u << i;
        } else if (u[i] == thr) {
            if (r < need) bits16 |= 1u << i;
            ++r;
        }
    }
    atomicOr(&s_mask[j >> 1], bits16 << ((j & 1) * 16));
    __syncthreads();
    if (j < NN / 32) g_maskbits[b * (NN / 32) + j] = s_mask[j];
}

// ---------------------------------------------------------------------------
// Fused persistent-style kernel. 2048 blocks x 256 threads, batch-major.
// Phases per block: stream+score -> (last 8 arrivals: helper reduce; last
// arrival: radix+publish) -> spin on mask flag -> masked write from L2.
// ---------------------------------------------------------------------------
__global__ void __launch_bounds__(256) k_fused(const float4* __restrict__ x4,
                                               float4* __restrict__ o4) {
    const int b      = blockIdx.x >> 8;
    const int blocal = blockIdx.x & 255;
    const int tid    = threadIdx.x;
    const int tb     = blocal * 256 + tid;     // 0..65535 within batch
    const int n4     = tb & 1023;
    const int cg     = (tb >> 10) & 3;
    const int t      = tb >> 12;

    // ---- Phase 1: stream x slice, compute cg-partial sums of squares ----
    const size_t xbase = ((size_t)(b * TT + t) * CC + cg * CPER) * (NN / 4) + n4;
    float a0 = 0.f, a1 = 0.f, a2 = 0.f, a3 = 0.f;
#pragma unroll
    for (int c = 0; c < CPER; ++c) {
        float4 v = x4[xbase + (size_t)c * (NN / 4)];
        a0 += v.x * v.x; a1 += v.y * v.y; a2 += v.z * v.z; a3 += v.w * v.w;
    }
    ((float4*)g_partial4)[((size_t)(b * TT + t) * CGROUPS + cg) * (NN / 4) + n4] =
        make_float4(a0, a1, a2, a3);

    __threadfence();                 // all threads: publish partial writes
    __syncthreads();
    __shared__ int s_role;
    if (tid == 0) s_role = atomicAdd(&g_cnt[b], 1);
    __syncthreads();
    const int role = s_role;

    // ---- Phase 2: last NHELP arrivals reduce scores; last one radixes ----
    if (role >= BLKS_PER_BATCH - NHELP) {
        if (tid == 0) {
            while (*(volatile int*)&g_cnt[b] != BLKS_PER_BATCH) __nanosleep(64);
        }
        __syncthreads();
        __threadfence();             // acquire: see all batch partials

        const int h = role - (BLKS_PER_BATCH - NHELP);   // 0..7
        const float* P = g_partial4 + (size_t)b * TT * CGROUPS * NN;
#pragma unroll
        for (int rep = 0; rep < 2; ++rep) {
            int n = h * 512 + rep * 256 + tid;
            float s = 0.f;
#pragma unroll
            for (int tt = 0; tt < TT; ++tt) {
                const float* pt = P + (size_t)(tt * CGROUPS) * NN + n;
                s += sqrtf(pt[0] + pt[NN] + pt[2 * NN] + pt[3 * NN]);
            }
            g_scores[b * NN + n] = s * (1.0f / (float)TT);
        }
        __threadfence();
        __syncthreads();
        if (tid == 0) atomicAdd(&g_cnt2[b], 1);

        if (role == BLKS_PER_BATCH - 1) {
            if (tid == 0) {
                while (*(volatile int*)&g_cnt2[b] != NHELP) __nanosleep(64);
            }
            __syncthreads();
            __threadfence();         // acquire: see all helper scores
            radix_select_256(b);
            __threadfence();
            __syncthreads();
            if (tid == 0) atomicExch(&g_flag[b], 1);   // release mask
        }
    }

    // ---- Phase 3: wait for mask, masked write-out from L2 ----
    if (tid == 0) {
        while (*(volatile int*)&g_flag[b] == 0) __nanosleep(128);
    }
    __syncthreads();
    __threadfence();                 // acquire: see mask bits

    const unsigned bits =
        (g_maskbits[b * (NN / 32) + (n4 >> 3)] >> ((n4 & 7) * 4)) & 0xFu;

    if (bits == 0u) {
        const float4 z = make_float4(0.f, 0.f, 0.f, 0.f);
#pragma unroll
        for (int c = 0; c < CPER; ++c)
            __stcs(&o4[xbase + (size_t)c * (NN / 4)], z);
    } else {
#pragma unroll
        for (int c = 0; c < CPER; ++c) {
            float4 v = __ldcs(&x4[xbase + (size_t)c * (NN / 4)]);
            v.x = (bits & 1u) ? v.x : 0.f;
            v.y = (bits & 2u) ? v.y : 0.f;
            v.z = (bits & 4u) ? v.z : 0.f;
            v.w = (bits & 8u) ? v.w : 0.f;
            __stcs(&o4[xbase + (size_t)c * (NN / 4)], v);
        }
    }

    // ---- Phase 4: last finisher resets batch state for graph replay ----
    __syncthreads();
    if (tid == 0) {
        __threadfence();
        int o3 = atomicAdd(&g_cnt3[b], 1);
        if (o3 == BLKS_PER_BATCH - 1) {
            g_cnt[b] = 0; g_cnt2[b] = 0; g_cnt3[b] = 0; g_flag[b] = 0;
            __threadfence();
        }
    }
}

// ---------------------------------------------------------------------------
extern "C" void kernel_launch(void* const* d_in, const int* in_sizes, int n_in,
                              void* d_out, int out_size) {
    const float* x = (const float*)d_in[0];
    float* out = (float*)d_out;

    // One launch: 8 batches x 256 blocks, batch-major (dispatch order keeps
    // the oldest incomplete batch fully resident -> spins are deadlock-free).
    k_fused<<<BB * BLKS_PER_BATCH, 256>>>((const float4*)x, (float4*)out);
}